// round 7
// baseline (speedup 1.0000x reference)
#include <cuda_runtime.h>
#include <cuda_bf16.h>
#include <cstdint>

// ---------------------------------------------------------------------------
// LinearTimeSelfAttention1d  (B=16, C=512, W=4096, H=8, D=64, G=32)
//
// Pipeline:
//   K1: groupnorm stats -> per-channel affine a[b,c], bb[b,c]
//   K2: beta[b,o] = w_qkv[o,:] . bb[b,:] + b_qkv[o]      (GN bias folded)
//   K3: qkv[b]   = (w_qkv * a[b]) @ x[b] + beta[b]       (1536x4096, fp32 SGEMM)
//   K5: pctx     = exp(k) @ v^T  (per (b,h), split over n) + partial Z
//   K5b: ctx     = sum(pctx)/Z
//   K6: Wc[b]    = per-head w_out . ctx^T                (fold out-proj)
//   K7: out[b]   = Wc[b] @ q[b] + b_out                  (512x4096, fp32 SGEMM)
// ---------------------------------------------------------------------------

#define BATCH 16
#define CH    512
#define WW    4096
#define HEADS 8
#define HDIM  64
#define GROUPS 32
#define QKV_M 1536
#define SPLITS 8

// -------------------- scratch (device globals, no runtime alloc) -----------
__device__ float g_qkv[(size_t)BATCH * QKV_M * WW];      // 384 MB
__device__ float g_a[BATCH * CH];
__device__ float g_bb[BATCH * CH];
__device__ float g_beta[BATCH * QKV_M];
__device__ float g_pctx[(size_t)BATCH * HEADS * SPLITS * HDIM * HDIM];
__device__ float g_pZ[BATCH * HEADS * SPLITS * HDIM];
__device__ float g_ctx[(size_t)BATCH * HEADS * HDIM * HDIM];
__device__ float g_Wc[(size_t)BATCH * CH * CH];

// -------------------- K1: group stats --------------------------------------
__global__ void __launch_bounds__(256) k1_stats(
    const float* __restrict__ x, const float* __restrict__ gn_w,
    const float* __restrict__ gn_b, float* __restrict__ ga, float* __restrict__ gbb)
{
    int bg = blockIdx.x;            // 0..511
    int b = bg >> 5, g = bg & 31;
    const float* p = x + ((size_t)b * CH + (size_t)g * 16) * WW;  // contiguous 65536 floats
    int tid = threadIdx.x;

    float s = 0.f, ss = 0.f;
    const float4* p4 = (const float4*)p;
    for (int i = tid; i < 16384; i += 256) {
        float4 v = p4[i];
        s  += v.x + v.y + v.z + v.w;
        ss += v.x*v.x + v.y*v.y + v.z*v.z + v.w*v.w;
    }
    #pragma unroll
    for (int off = 16; off; off >>= 1) {
        s  += __shfl_down_sync(0xffffffffu, s,  off);
        ss += __shfl_down_sync(0xffffffffu, ss, off);
    }
    __shared__ float sS[8], sSS[8];
    int warp = tid >> 5, lane = tid & 31;
    if (lane == 0) { sS[warp] = s; sSS[warp] = ss; }
    __syncthreads();
    if (tid == 0) {
        float S = 0.f, SS = 0.f;
        #pragma unroll
        for (int w = 0; w < 8; w++) { S += sS[w]; SS += sSS[w]; }
        sS[0] = S; sSS[0] = SS;
    }
    __syncthreads();
    float mu   = sS[0]  * (1.f / 65536.f);
    float var  = sSS[0] * (1.f / 65536.f) - mu * mu;
    float rstd = rsqrtf(var + 1e-5f);
    if (tid < 16) {
        int c = g * 16 + tid;
        float w = gn_w[c];
        ga [b * CH + c] = w * rstd;
        gbb[b * CH + c] = gn_b[c] - mu * rstd * w;
    }
}

// -------------------- K2: beta GEMV ----------------------------------------
__global__ void __launch_bounds__(256) k2_beta(
    const float* __restrict__ w_qkv, const float* __restrict__ b_qkv,
    const float* __restrict__ gbb, float* __restrict__ gbeta)
{
    int b = blockIdx.y;
    int o = blockIdx.x * 8 + (threadIdx.x >> 5);
    int lane = threadIdx.x & 31;
    const float* wrow = w_qkv + (size_t)o * CH;
    const float* bb = gbb + b * CH;
    float s = 0.f;
    for (int c = lane; c < CH; c += 32) s += wrow[c] * bb[c];
    #pragma unroll
    for (int off = 16; off; off >>= 1) s += __shfl_down_sync(0xffffffffu, s, off);
    if (lane == 0) gbeta[b * QKV_M + o] = s + b_qkv[o];
}

// -------------------- generic 128x128x8 fp32 SGEMM --------------------------
// C[b] = (A[b] scaled by scale[b] along K) @ B[b] + bias[b][row]
__global__ void __launch_bounds__(256) sgemm128(
    const float* __restrict__ Abase, long sA,
    const float* __restrict__ scaleBase, long sScale,
    const float* __restrict__ Bbase, long sB,
    const float* __restrict__ biasBase, long sBias,
    float* __restrict__ Cbase, long sC,
    int N, int K)
{
    const float* A    = Abase + (long)blockIdx.z * sA;
    const float* Bp   = Bbase + (long)blockIdx.z * sB;
    const float* bias = biasBase + (long)blockIdx.z * sBias;
    const float* scale = scaleBase ? scaleBase + (long)blockIdx.z * sScale : nullptr;
    float* C = Cbase + (long)blockIdx.z * sC;

    __shared__ float As[8][128];
    __shared__ float Bs[8][128];
    int tid = threadIdx.x;
    int tile_m = blockIdx.y * 128, tile_n = blockIdx.x * 128;
    int arow = tid >> 1, acol = (tid & 1) << 2;
    int brow = tid >> 5, bcol = (tid & 31) << 2;
    int ty = tid >> 4, tx = tid & 15;

    const float* Aptr = A + (long)(tile_m + arow) * K + acol;
    const float* Bptr = Bp + (long)brow * N + tile_n + bcol;

    float acc[8][8];
    #pragma unroll
    for (int i = 0; i < 8; i++)
        #pragma unroll
        for (int j = 0; j < 8; j++) acc[i][j] = 0.f;

    for (int k0 = 0; k0 < K; k0 += 8) {
        float4 av = *(const float4*)Aptr;  Aptr += 8;
        if (scale) {
            const float* sc = scale + k0 + acol;
            av.x *= sc[0]; av.y *= sc[1]; av.z *= sc[2]; av.w *= sc[3];
        }
        float4 bv = *(const float4*)Bptr;  Bptr += (long)8 * N;
        As[acol + 0][arow] = av.x;
        As[acol + 1][arow] = av.y;
        As[acol + 2][arow] = av.z;
        As[acol + 3][arow] = av.w;
        *(float4*)&Bs[brow][bcol] = bv;
        __syncthreads();

        #pragma unroll
        for (int kk = 0; kk < 8; kk++) {
            float aF[8], bF[8];
            *(float4*)(aF)     = *(const float4*)&As[kk][ty * 8];
            *(float4*)(aF + 4) = *(const float4*)&As[kk][ty * 8 + 4];
            *(float4*)(bF)     = *(const float4*)&Bs[kk][tx * 8];
            *(float4*)(bF + 4) = *(const float4*)&Bs[kk][tx * 8 + 4];
            #pragma unroll
            for (int i = 0; i < 8; i++)
                #pragma unroll
                for (int j = 0; j < 8; j++)
                    acc[i][j] += aF[i] * bF[j];
        }
        __syncthreads();
    }

    #pragma unroll
    for (int i = 0; i < 8; i++) {
        int row = tile_m + ty * 8 + i;
        float bvl = bias[row];
        float4 o0 = {acc[i][0] + bvl, acc[i][1] + bvl, acc[i][2] + bvl, acc[i][3] + bvl};
        float4 o1 = {acc[i][4] + bvl, acc[i][5] + bvl, acc[i][6] + bvl, acc[i][7] + bvl};
        float* cp = C + (long)row * N + tile_n + tx * 8;
        *(float4*)(cp)     = o0;
        *(float4*)(cp + 4) = o1;
    }
}

// -------------------- K5: partial context + partial Z -----------------------
__global__ void __launch_bounds__(256) k5_ctx_partial(
    const float* __restrict__ qkv, float* __restrict__ pctx, float* __restrict__ pZ)
{
    int split = blockIdx.x, h = blockIdx.y, b = blockIdx.z;
    const float* kb = qkv + ((size_t)b * QKV_M + 512  + h * HDIM) * WW + split * 512;
    const float* vb = qkv + ((size_t)b * QKV_M + 1024 + h * HDIM) * WW + split * 512;

    __shared__ float ekT[16][64];
    __shared__ float vT [16][64];
    int tid = threadIdx.x;
    int ld_d = tid >> 2, ld_n4 = (tid & 3) << 2;
    int ty = tid >> 4, tx = tid & 15;

    float acc[4][4];
    #pragma unroll
    for (int i = 0; i < 4; i++)
        #pragma unroll
        for (int j = 0; j < 4; j++) acc[i][j] = 0.f;
    float zacc = 0.f;

    for (int nc = 0; nc < 512; nc += 16) {
        float4 kv4 = *(const float4*)(kb + (long)ld_d * WW + nc + ld_n4);
        float4 vv4 = *(const float4*)(vb + (long)ld_d * WW + nc + ld_n4);
        ekT[ld_n4 + 0][ld_d] = __expf(kv4.x);
        ekT[ld_n4 + 1][ld_d] = __expf(kv4.y);
        ekT[ld_n4 + 2][ld_d] = __expf(kv4.z);
        ekT[ld_n4 + 3][ld_d] = __expf(kv4.w);
        vT [ld_n4 + 0][ld_d] = vv4.x;
        vT [ld_n4 + 1][ld_d] = vv4.y;
        vT [ld_n4 + 2][ld_d] = vv4.z;
        vT [ld_n4 + 3][ld_d] = vv4.w;
        __syncthreads();

        if (tid < 64) {
            #pragma unroll
            for (int nn = 0; nn < 16; nn++) zacc += ekT[nn][tid];
        }
        #pragma unroll
        for (int nn = 0; nn < 16; nn++) {
            float a0[4], b0[4];
            *(float4*)a0 = *(const float4*)&ekT[nn][ty * 4];
            *(float4*)b0 = *(const float4*)&vT [nn][tx * 4];
            #pragma unroll
            for (int i = 0; i < 4; i++)
                #pragma unroll
                for (int j = 0; j < 4; j++)
                    acc[i][j] += a0[i] * b0[j];
        }
        __syncthreads();
    }

    size_t base = (((size_t)(b * HEADS + h)) * SPLITS + split) * (HDIM * HDIM);
    #pragma unroll
    for (int i = 0; i < 4; i++)
        #pragma unroll
        for (int j = 0; j < 4; j++)
            pctx[base + (ty * 4 + i) * HDIM + tx * 4 + j] = acc[i][j];
    if (tid < 64)
        pZ[((b * HEADS + h) * SPLITS + split) * HDIM + tid] = zacc;
}

// -------------------- K5b: reduce splits + normalize ------------------------
__global__ void __launch_bounds__(256) k5b_reduce(
    const float* __restrict__ pctx, const float* __restrict__ pZ, float* __restrict__ ctx)
{
    int bh = blockIdx.x;   // 0..127
    __shared__ float zs[64];
    if (threadIdx.x < 64) {
        float z = 0.f;
        #pragma unroll
        for (int s = 0; s < SPLITS; s++) z += pZ[(bh * SPLITS + s) * HDIM + threadIdx.x];
        zs[threadIdx.x] = 1.f / z;
    }
    __syncthreads();
    for (int idx = threadIdx.x; idx < HDIM * HDIM; idx += 256) {
        float a = 0.f;
        #pragma unroll
        for (int s = 0; s < SPLITS; s++)
            a += pctx[((size_t)bh * SPLITS + s) * (HDIM * HDIM) + idx];
        ctx[(size_t)bh * (HDIM * HDIM) + idx] = a * zs[idx >> 6];
    }
}

// -------------------- K6: Wc[b][o][h*64+d] = sum_e w_out[o,he] ctx[h,d,e] ---
__global__ void __launch_bounds__(256) k6_wc(
    const float* __restrict__ w_out, const float* __restrict__ ctx, float* __restrict__ Wc)
{
    int h = blockIdx.x, b = blockIdx.y;
    __shared__ float cs[64][65];
    int bh = b * HEADS + h;
    for (int t = threadIdx.x; t < HDIM * HDIM; t += 256)
        cs[t >> 6][t & 63] = ctx[(size_t)bh * (HDIM * HDIM) + t];
    __syncthreads();

    #pragma unroll
    for (int rep = 0; rep < 2; rep++) {
        int o = (rep << 8) + threadIdx.x;
        const float* wrow = w_out + (size_t)o * CH + h * HDIM;
        float wc[64];
        #pragma unroll
        for (int e = 0; e < 64; e++) wc[e] = wrow[e];
        float* outp = Wc + ((size_t)b * CH + o) * CH + h * HDIM;
        for (int d = 0; d < 64; d++) {
            float s = 0.f;
            #pragma unroll
            for (int e = 0; e < 64; e++) s += wc[e] * cs[d][e];
            outp[d] = s;
        }
    }
}

// -------------------- launch -----------------------------------------------
extern "C" void kernel_launch(void* const* d_in, const int* in_sizes, int n_in,
                              void* d_out, int out_size)
{
    const float* x     = (const float*)d_in[0];
    const float* gn_w  = (const float*)d_in[1];
    const float* gn_b  = (const float*)d_in[2];
    const float* w_qkv = (const float*)d_in[3];
    const float* b_qkv = (const float*)d_in[4];
    const float* w_out = (const float*)d_in[5];
    const float* b_out = (const float*)d_in[6];
    float* out = (float*)d_out;

    float *p_qkv, *p_a, *p_bb, *p_beta, *p_pctx, *p_pZ, *p_ctx, *p_Wc;
    cudaGetSymbolAddress((void**)&p_qkv,  g_qkv);
    cudaGetSymbolAddress((void**)&p_a,    g_a);
    cudaGetSymbolAddress((void**)&p_bb,   g_bb);
    cudaGetSymbolAddress((void**)&p_beta, g_beta);
    cudaGetSymbolAddress((void**)&p_pctx, g_pctx);
    cudaGetSymbolAddress((void**)&p_pZ,   g_pZ);
    cudaGetSymbolAddress((void**)&p_ctx,  g_ctx);
    cudaGetSymbolAddress((void**)&p_Wc,   g_Wc);

    // K1: group stats
    k1_stats<<<BATCH * GROUPS, 256>>>(x, gn_w, gn_b, p_a, p_bb);

    // K2: folded bias
    k2_beta<<<dim3(QKV_M / 8, BATCH), 256>>>(w_qkv, b_qkv, p_bb, p_beta);

    // K3: QKV GEMM (A = w_qkv shared, scaled by a[b] along K; B = x[b])
    sgemm128<<<dim3(WW / 128, QKV_M / 128, BATCH), 256>>>(
        w_qkv, 0L,
        p_a, (long)CH,
        x, (long)CH * WW,
        p_beta, (long)QKV_M,
        p_qkv, (long)QKV_M * WW,
        WW, CH);

    // K5: context partials (+Z)
    k5_ctx_partial<<<dim3(SPLITS, HEADS, BATCH), 256>>>(p_qkv, p_pctx, p_pZ);

    // K5b: reduce + normalize
    k5b_reduce<<<BATCH * HEADS, 256>>>(p_pctx, p_pZ, p_ctx);

    // K6: fold out-projection with context
    k6_wc<<<dim3(HEADS, BATCH), 256>>>(w_out, p_ctx, p_Wc);

    // K7: final GEMM  out[b] = Wc[b] @ q[b] + b_out
    sgemm128<<<dim3(WW / 128, CH / 128, BATCH), 256>>>(
        p_Wc, (long)CH * CH,
        nullptr, 0L,
        p_qkv, (long)QKV_M * WW,   // q = rows [0,512) of qkv[b]
        b_out, 0L,
        out, (long)CH * WW,
        WW, CH);
}

// round 8
// speedup vs baseline: 2.7056x; 2.7056x over previous
#include <cuda_runtime.h>
#include <cuda_bf16.h>
#include <cstdint>

// ---------------------------------------------------------------------------
// LinearTimeSelfAttention1d  (B=16, C=512, W=4096, H=8, D=64, G=32)
//
//   K1: groupnorm stats -> per-channel affine a[b,c], bb[b,c]
//   K2: beta[b,o] = w_qkv[o,:] . bb[b,:] + b_qkv[o]
//   K3: qkv[b]   = (w_qkv * a[b]) @ x[b] + beta[b]     (tf32 tensor GEMM)
//   K5: pctx     = exp(k) @ v^T  (split over n) + partial Z
//   K5b: ctx     = sum(pctx)/Z
//   K6: Wc[b]    = per-head w_out . ctx^T
//   K7: out[b]   = Wc[b] @ q[b] + b_out                (tf32 tensor GEMM)
// ---------------------------------------------------------------------------

#define BATCH 16
#define CH    512
#define WW    4096
#define HEADS 8
#define HDIM  64
#define GROUPS 32
#define QKV_M 1536
#define SPLITS 8

// -------------------- scratch (device globals, no runtime alloc) -----------
__device__ float g_qkv[(size_t)BATCH * QKV_M * WW];      // 384 MB
__device__ float g_a[BATCH * CH];
__device__ float g_bb[BATCH * CH];
__device__ float g_beta[BATCH * QKV_M];
__device__ float g_pctx[(size_t)BATCH * HEADS * SPLITS * HDIM * HDIM];
__device__ float g_pZ[BATCH * HEADS * SPLITS * HDIM];
__device__ float g_ctx[(size_t)BATCH * HEADS * HDIM * HDIM];
__device__ float g_Wc[(size_t)BATCH * CH * CH];

// -------------------- K1: group stats --------------------------------------
__global__ void __launch_bounds__(256) k1_stats(
    const float* __restrict__ x, const float* __restrict__ gn_w,
    const float* __restrict__ gn_b, float* __restrict__ ga, float* __restrict__ gbb)
{
    int bg = blockIdx.x;
    int b = bg >> 5, g = bg & 31;
    const float* p = x + ((size_t)b * CH + (size_t)g * 16) * WW;
    int tid = threadIdx.x;

    float s = 0.f, ss = 0.f;
    const float4* p4 = (const float4*)p;
    for (int i = tid; i < 16384; i += 256) {
        float4 v = p4[i];
        s  += v.x + v.y + v.z + v.w;
        ss += v.x*v.x + v.y*v.y + v.z*v.z + v.w*v.w;
    }
    #pragma unroll
    for (int off = 16; off; off >>= 1) {
        s  += __shfl_down_sync(0xffffffffu, s,  off);
        ss += __shfl_down_sync(0xffffffffu, ss, off);
    }
    __shared__ float sS[8], sSS[8];
    int warp = tid >> 5, lane = tid & 31;
    if (lane == 0) { sS[warp] = s; sSS[warp] = ss; }
    __syncthreads();
    if (tid == 0) {
        float S = 0.f, SS = 0.f;
        #pragma unroll
        for (int w = 0; w < 8; w++) { S += sS[w]; SS += sSS[w]; }
        sS[0] = S; sSS[0] = SS;
    }
    __syncthreads();
    float mu   = sS[0]  * (1.f / 65536.f);
    float var  = sSS[0] * (1.f / 65536.f) - mu * mu;
    float rstd = rsqrtf(var + 1e-5f);
    if (tid < 16) {
        int c = g * 16 + tid;
        float w = gn_w[c];
        ga [b * CH + c] = w * rstd;
        gbb[b * CH + c] = gn_b[c] - mu * rstd * w;
    }
}

// -------------------- K2: beta GEMV ----------------------------------------
__global__ void __launch_bounds__(256) k2_beta(
    const float* __restrict__ w_qkv, const float* __restrict__ b_qkv,
    const float* __restrict__ gbb, float* __restrict__ gbeta)
{
    int b = blockIdx.y;
    int o = blockIdx.x * 8 + (threadIdx.x >> 5);
    int lane = threadIdx.x & 31;
    const float* wrow = w_qkv + (size_t)o * CH;
    const float* bb = gbb + b * CH;
    float s = 0.f;
    for (int c = lane; c < CH; c += 32) s += wrow[c] * bb[c];
    #pragma unroll
    for (int off = 16; off; off >>= 1) s += __shfl_down_sync(0xffffffffu, s, off);
    if (lane == 0) gbeta[b * QKV_M + o] = s + b_qkv[o];
}

// -------------------- tf32 helpers -----------------------------------------
__device__ __forceinline__ uint32_t f2tf(float f) {
    uint32_t u;
    asm("cvt.rna.tf32.f32 %0, %1;" : "=r"(u) : "f"(f));
    return u;
}

__device__ __forceinline__ void mma_tf32(float* c,
    uint32_t a0, uint32_t a1, uint32_t a2, uint32_t a3,
    uint32_t b0, uint32_t b1)
{
    asm volatile(
        "mma.sync.aligned.m16n8k8.row.col.f32.tf32.tf32.f32 "
        "{%0,%1,%2,%3}, {%4,%5,%6,%7}, {%8,%9}, {%0,%1,%2,%3};"
        : "+f"(c[0]), "+f"(c[1]), "+f"(c[2]), "+f"(c[3])
        : "r"(a0), "r"(a1), "r"(a2), "r"(a3), "r"(b0), "r"(b1));
}

// -------------------- tf32 tensor-core 128x128 GEMM -------------------------
// C[b](MxN) = (A[b] scaled along K by scale[b]) @ B[b] + bias[b][row]
// A row-major [M][K], B row-major [K][N], K multiple of 16.
__global__ void __launch_bounds__(256) gemm_tf32(
    const float* __restrict__ Abase, long sA,
    const float* __restrict__ scaleBase, long sScale,
    const float* __restrict__ Bbase, long sB,
    const float* __restrict__ biasBase, long sBias,
    float* __restrict__ Cbase, long sC,
    int N, int K)
{
    const float* A    = Abase + (long)blockIdx.z * sA;
    const float* Bp   = Bbase + (long)blockIdx.z * sB;
    const float* bias = biasBase + (long)blockIdx.z * sBias;
    const float* scale = scaleBase ? scaleBase + (long)blockIdx.z * sScale : nullptr;
    float* C = Cbase + (long)blockIdx.z * sC;

    // A: row-major [m 128][k 16], stride 20 -> conflict-free A-fragment LDS
    // B: k-major [k 16][n 128], stride 136 -> conflict-free B-fragment LDS
    __shared__ uint32_t As[128][20];
    __shared__ uint32_t Bs[16][136];

    int tid  = threadIdx.x;
    int lane = tid & 31, warp = tid >> 5;
    int g    = lane >> 2, tig = lane & 3;
    int wm   = (warp & 1) * 64;    // warp m-offset
    int wn   = (warp >> 1) * 32;   // warp n-offset
    int tile_m = blockIdx.y * 128, tile_n = blockIdx.x * 128;

    // A fill: row = tid>>2 (+0,+64), kc = (tid&3)*4   (coalesced 64B/row-group)
    int ar = tid >> 2, akc = (tid & 3) * 4;
    // B fill: krow = tid>>5 (+0,+8), col = (tid&31)*4 (fully coalesced)
    int bkr = tid >> 5, bc = (tid & 31) * 4;

    const float* Aptr = A  + (long)(tile_m + ar) * K + akc;
    const float* Bptr = Bp + (long)bkr * N + tile_n + bc;

    float acc[4][4][4];
    #pragma unroll
    for (int i = 0; i < 4; i++)
        #pragma unroll
        for (int j = 0; j < 4; j++)
            #pragma unroll
            for (int r = 0; r < 4; r++) acc[i][j][r] = 0.f;

    // prefetch stage 0
    float4 aR0 = *(const float4*)Aptr;
    float4 aR1 = *(const float4*)(Aptr + (long)64 * K);
    float4 bR0 = *(const float4*)Bptr;
    float4 bR1 = *(const float4*)(Bptr + (long)8 * N);
    float4 sR = {1.f, 1.f, 1.f, 1.f};
    if (scale) {
        const float* sp = scale + akc;
        sR.x = sp[0]; sR.y = sp[1]; sR.z = sp[2]; sR.w = sp[3];
    }

    for (int k0 = 0; k0 < K; k0 += 16) {
        // ---- store stage to smem (apply GN scale + tf32 convert on A) ----
        {
            float4 a0 = aR0, a1 = aR1;
            a0.x *= sR.x; a0.y *= sR.y; a0.z *= sR.z; a0.w *= sR.w;
            a1.x *= sR.x; a1.y *= sR.y; a1.z *= sR.z; a1.w *= sR.w;
            uint4 u0 = {f2tf(a0.x), f2tf(a0.y), f2tf(a0.z), f2tf(a0.w)};
            uint4 u1 = {f2tf(a1.x), f2tf(a1.y), f2tf(a1.z), f2tf(a1.w)};
            *(uint4*)&As[ar][akc]      = u0;
            *(uint4*)&As[ar + 64][akc] = u1;
            uint4 v0 = {f2tf(bR0.x), f2tf(bR0.y), f2tf(bR0.z), f2tf(bR0.w)};
            uint4 v1 = {f2tf(bR1.x), f2tf(bR1.y), f2tf(bR1.z), f2tf(bR1.w)};
            *(uint4*)&Bs[bkr][bc]     = v0;
            *(uint4*)&Bs[bkr + 8][bc] = v1;
        }
        __syncthreads();

        // ---- prefetch next stage (overlaps with MMA below) ----
        if (k0 + 16 < K) {
            Aptr += 16;
            Bptr += (long)16 * N;
            aR0 = *(const float4*)Aptr;
            aR1 = *(const float4*)(Aptr + (long)64 * K);
            bR0 = *(const float4*)Bptr;
            bR1 = *(const float4*)(Bptr + (long)8 * N);
            if (scale) {
                const float* sp = scale + k0 + 16 + akc;
                sR.x = sp[0]; sR.y = sp[1]; sR.z = sp[2]; sR.w = sp[3];
            }
        }

        // ---- compute: 2 x (m16n8k8 over 4x4 fragment grid) ----
        #pragma unroll
        for (int ks = 0; ks < 16; ks += 8) {
            uint32_t bf[4][2];
            #pragma unroll
            for (int ni = 0; ni < 4; ni++) {
                bf[ni][0] = Bs[ks + tig][wn + ni * 8 + g];
                bf[ni][1] = Bs[ks + tig + 4][wn + ni * 8 + g];
            }
            #pragma unroll
            for (int mi = 0; mi < 4; mi++) {
                int m0 = wm + mi * 16 + g;
                uint32_t a0 = As[m0][ks + tig];
                uint32_t a1 = As[m0 + 8][ks + tig];
                uint32_t a2 = As[m0][ks + tig + 4];
                uint32_t a3 = As[m0 + 8][ks + tig + 4];
                #pragma unroll
                for (int ni = 0; ni < 4; ni++)
                    mma_tf32(acc[mi][ni], a0, a1, a2, a3, bf[ni][0], bf[ni][1]);
            }
        }
        __syncthreads();
    }

    // ---- epilogue: +bias, float2 stores ----
    #pragma unroll
    for (int mi = 0; mi < 4; mi++) {
        int r0 = tile_m + wm + mi * 16 + g;
        int r1 = r0 + 8;
        float bv0 = bias[r0], bv1 = bias[r1];
        #pragma unroll
        for (int ni = 0; ni < 4; ni++) {
            int col = tile_n + wn + ni * 8 + 2 * tig;
            float2 v0 = {acc[mi][ni][0] + bv0, acc[mi][ni][1] + bv0};
            float2 v1 = {acc[mi][ni][2] + bv1, acc[mi][ni][3] + bv1};
            *(float2*)(C + (long)r0 * N + col) = v0;
            *(float2*)(C + (long)r1 * N + col) = v1;
        }
    }
}

// -------------------- K5: partial context + partial Z -----------------------
__global__ void __launch_bounds__(256) k5_ctx_partial(
    const float* __restrict__ qkv, float* __restrict__ pctx, float* __restrict__ pZ)
{
    int split = blockIdx.x, h = blockIdx.y, b = blockIdx.z;
    const float* kb = qkv + ((size_t)b * QKV_M + 512  + h * HDIM) * WW + split * 512;
    const float* vb = qkv + ((size_t)b * QKV_M + 1024 + h * HDIM) * WW + split * 512;

    __shared__ float ekT[16][64];
    __shared__ float vT [16][64];
    int tid = threadIdx.x;
    int ld_d = tid >> 2, ld_n4 = (tid & 3) << 2;
    int ty = tid >> 4, tx = tid & 15;

    float acc[4][4];
    #pragma unroll
    for (int i = 0; i < 4; i++)
        #pragma unroll
        for (int j = 0; j < 4; j++) acc[i][j] = 0.f;
    float zacc = 0.f;

    for (int nc = 0; nc < 512; nc += 16) {
        float4 kv4 = *(const float4*)(kb + (long)ld_d * WW + nc + ld_n4);
        float4 vv4 = *(const float4*)(vb + (long)ld_d * WW + nc + ld_n4);
        ekT[ld_n4 + 0][ld_d] = __expf(kv4.x);
        ekT[ld_n4 + 1][ld_d] = __expf(kv4.y);
        ekT[ld_n4 + 2][ld_d] = __expf(kv4.z);
        ekT[ld_n4 + 3][ld_d] = __expf(kv4.w);
        vT [ld_n4 + 0][ld_d] = vv4.x;
        vT [ld_n4 + 1][ld_d] = vv4.y;
        vT [ld_n4 + 2][ld_d] = vv4.z;
        vT [ld_n4 + 3][ld_d] = vv4.w;
        __syncthreads();

        if (tid < 64) {
            #pragma unroll
            for (int nn = 0; nn < 16; nn++) zacc += ekT[nn][tid];
        }
        #pragma unroll
        for (int nn = 0; nn < 16; nn++) {
            float a0[4], b0[4];
            *(float4*)a0 = *(const float4*)&ekT[nn][ty * 4];
            *(float4*)b0 = *(const float4*)&vT [nn][tx * 4];
            #pragma unroll
            for (int i = 0; i < 4; i++)
                #pragma unroll
                for (int j = 0; j < 4; j++)
                    acc[i][j] += a0[i] * b0[j];
        }
        __syncthreads();
    }

    size_t base = (((size_t)(b * HEADS + h)) * SPLITS + split) * (HDIM * HDIM);
    #pragma unroll
    for (int i = 0; i < 4; i++)
        #pragma unroll
        for (int j = 0; j < 4; j++)
            pctx[base + (ty * 4 + i) * HDIM + tx * 4 + j] = acc[i][j];
    if (tid < 64)
        pZ[((b * HEADS + h) * SPLITS + split) * HDIM + tid] = zacc;
}

// -------------------- K5b: reduce splits + normalize ------------------------
__global__ void __launch_bounds__(256) k5b_reduce(
    const float* __restrict__ pctx, const float* __restrict__ pZ, float* __restrict__ ctx)
{
    int bh = blockIdx.x;
    __shared__ float zs[64];
    if (threadIdx.x < 64) {
        float z = 0.f;
        #pragma unroll
        for (int s = 0; s < SPLITS; s++) z += pZ[(bh * SPLITS + s) * HDIM + threadIdx.x];
        zs[threadIdx.x] = 1.f / z;
    }
    __syncthreads();
    for (int idx = threadIdx.x; idx < HDIM * HDIM; idx += 256) {
        float a = 0.f;
        #pragma unroll
        for (int s = 0; s < SPLITS; s++)
            a += pctx[((size_t)bh * SPLITS + s) * (HDIM * HDIM) + idx];
        ctx[(size_t)bh * (HDIM * HDIM) + idx] = a * zs[idx >> 6];
    }
}

// -------------------- K6: Wc[b][o][h*64+d] = sum_e w_out[o,he] ctx[h,d,e] ---
__global__ void __launch_bounds__(256) k6_wc(
    const float* __restrict__ w_out, const float* __restrict__ ctx, float* __restrict__ Wc)
{
    int h = blockIdx.x, b = blockIdx.y;
    __shared__ float cs[64][65];
    int bh = b * HEADS + h;
    for (int t = threadIdx.x; t < HDIM * HDIM; t += 256)
        cs[t >> 6][t & 63] = ctx[(size_t)bh * (HDIM * HDIM) + t];
    __syncthreads();

    #pragma unroll
    for (int rep = 0; rep < 2; rep++) {
        int o = (rep << 8) + threadIdx.x;
        const float* wrow = w_out + (size_t)o * CH + h * HDIM;
        float wc[64];
        #pragma unroll
        for (int e = 0; e < 64; e++) wc[e] = wrow[e];
        float* outp = Wc + ((size_t)b * CH + o) * CH + h * HDIM;
        for (int d = 0; d < 64; d++) {
            float s = 0.f;
            #pragma unroll
            for (int e = 0; e < 64; e++) s += wc[e] * cs[d][e];
            outp[d] = s;
        }
    }
}

// -------------------- launch -----------------------------------------------
extern "C" void kernel_launch(void* const* d_in, const int* in_sizes, int n_in,
                              void* d_out, int out_size)
{
    const float* x     = (const float*)d_in[0];
    const float* gn_w  = (const float*)d_in[1];
    const float* gn_b  = (const float*)d_in[2];
    const float* w_qkv = (const float*)d_in[3];
    const float* b_qkv = (const float*)d_in[4];
    const float* w_out = (const float*)d_in[5];
    const float* b_out = (const float*)d_in[6];
    float* out = (float*)d_out;

    float *p_qkv, *p_a, *p_bb, *p_beta, *p_pctx, *p_pZ, *p_ctx, *p_Wc;
    cudaGetSymbolAddress((void**)&p_qkv,  g_qkv);
    cudaGetSymbolAddress((void**)&p_a,    g_a);
    cudaGetSymbolAddress((void**)&p_bb,   g_bb);
    cudaGetSymbolAddress((void**)&p_beta, g_beta);
    cudaGetSymbolAddress((void**)&p_pctx, g_pctx);
    cudaGetSymbolAddress((void**)&p_pZ,   g_pZ);
    cudaGetSymbolAddress((void**)&p_ctx,  g_ctx);
    cudaGetSymbolAddress((void**)&p_Wc,   g_Wc);

    // K1: group stats
    k1_stats<<<BATCH * GROUPS, 256>>>(x, gn_w, gn_b, p_a, p_bb);

    // K2: folded bias
    k2_beta<<<dim3(QKV_M / 8, BATCH), 256>>>(w_qkv, b_qkv, p_bb, p_beta);

    // K3: QKV GEMM (tf32 tensor cores; A = w_qkv scaled by a[b] along K)
    gemm_tf32<<<dim3(WW / 128, QKV_M / 128, BATCH), 256>>>(
        w_qkv, 0L,
        p_a, (long)CH,
        x, (long)CH * WW,
        p_beta, (long)QKV_M,
        p_qkv, (long)QKV_M * WW,
        WW, CH);

    // K5: context partials (+Z)
    k5_ctx_partial<<<dim3(SPLITS, HEADS, BATCH), 256>>>(p_qkv, p_pctx, p_pZ);

    // K5b: reduce + normalize
    k5b_reduce<<<BATCH * HEADS, 256>>>(p_pctx, p_pZ, p_ctx);

    // K6: fold out-projection with context
    k6_wc<<<dim3(HEADS, BATCH), 256>>>(w_out, p_ctx, p_Wc);

    // K7: final GEMM (tf32 tensor cores)  out[b] = Wc[b] @ q[b] + b_out
    gemm_tf32<<<dim3(WW / 128, CH / 128, BATCH), 256>>>(
        p_Wc, (long)CH * CH,
        nullptr, 0L,
        p_qkv, (long)QKV_M * WW,   // q = rows [0,512) of qkv[b]
        b_out, 0L,
        out, (long)CH * WW,
        WW, CH);
}

// round 10
// speedup vs baseline: 2.9319x; 1.0836x over previous
#include <cuda_runtime.h>
#include <cuda_bf16.h>
#include <cuda_fp16.h>
#include <cstdint>

// ---------------------------------------------------------------------------
// LinearTimeSelfAttention1d  (B=16, C=512, W=4096, H=8, D=64, G=32)
//
//   K1: groupnorm stats -> per-channel affine a[b,c], bb[b,c]
//   K2: beta[b,o] = w_qkv[o,:] . bb[b,:] + b_qkv[o]
//   K3: qkv[b]   = (w_qkv * a[b]) @ x[b] + beta[b]     (fp16 tensor GEMM, fp32 acc)
//   K5: pctx     = exp(k) @ v^T  (split over n) + partial Z
//   K5b: ctx     = sum(pctx)/Z
//   K6: Wc[b]    = per-head w_out . ctx^T
//   K7: out[b]   = Wc[b] @ q[b] + b_out                (fp16 tensor GEMM, fp32 acc)
// ---------------------------------------------------------------------------

#define BATCH 16
#define CH    512
#define WW    4096
#define HEADS 8
#define HDIM  64
#define GROUPS 32
#define QKV_M 1536
#define SPLITS 8

// -------------------- scratch (device globals, no runtime alloc) -----------
__device__ float g_qkv[(size_t)BATCH * QKV_M * WW];      // 384 MB
__device__ float g_a[BATCH * CH];
__device__ float g_bb[BATCH * CH];
__device__ float g_beta[BATCH * QKV_M];
__device__ float g_pctx[(size_t)BATCH * HEADS * SPLITS * HDIM * HDIM];
__device__ float g_pZ[BATCH * HEADS * SPLITS * HDIM];
__device__ float g_ctx[(size_t)BATCH * HEADS * HDIM * HDIM];
__device__ float g_Wc[(size_t)BATCH * CH * CH];

// -------------------- K1: group stats --------------------------------------
__global__ void __launch_bounds__(256) k1_stats(
    const float* __restrict__ x, const float* __restrict__ gn_w,
    const float* __restrict__ gn_b, float* __restrict__ ga, float* __restrict__ gbb)
{
    int bg = blockIdx.x;
    int b = bg >> 5, g = bg & 31;
    const float* p = x + ((size_t)b * CH + (size_t)g * 16) * WW;
    int tid = threadIdx.x;

    float s = 0.f, ss = 0.f;
    const float4* p4 = (const float4*)p;
    for (int i = tid; i < 16384; i += 256) {
        float4 v = p4[i];
        s  += v.x + v.y + v.z + v.w;
        ss += v.x*v.x + v.y*v.y + v.z*v.z + v.w*v.w;
    }
    #pragma unroll
    for (int off = 16; off; off >>= 1) {
        s  += __shfl_down_sync(0xffffffffu, s,  off);
        ss += __shfl_down_sync(0xffffffffu, ss, off);
    }
    __shared__ float sS[8], sSS[8];
    int warp = tid >> 5, lane = tid & 31;
    if (lane == 0) { sS[warp] = s; sSS[warp] = ss; }
    __syncthreads();
    if (tid == 0) {
        float S = 0.f, SS = 0.f;
        #pragma unroll
        for (int w = 0; w < 8; w++) { S += sS[w]; SS += sSS[w]; }
        sS[0] = S; sSS[0] = SS;
    }
    __syncthreads();
    float mu   = sS[0]  * (1.f / 65536.f);
    float var  = sSS[0] * (1.f / 65536.f) - mu * mu;
    float rstd = rsqrtf(var + 1e-5f);
    if (tid < 16) {
        int c = g * 16 + tid;
        float w = gn_w[c];
        ga [b * CH + c] = w * rstd;
        gbb[b * CH + c] = gn_b[c] - mu * rstd * w;
    }
}

// -------------------- K2: beta GEMV ----------------------------------------
__global__ void __launch_bounds__(256) k2_beta(
    const float* __restrict__ w_qkv, const float* __restrict__ b_qkv,
    const float* __restrict__ gbb, float* __restrict__ gbeta)
{
    int b = blockIdx.y;
    int o = blockIdx.x * 8 + (threadIdx.x >> 5);
    int lane = threadIdx.x & 31;
    const float* wrow = w_qkv + (size_t)o * CH;
    const float* bb = gbb + b * CH;
    float s = 0.f;
    for (int c = lane; c < CH; c += 32) s += wrow[c] * bb[c];
    #pragma unroll
    for (int off = 16; off; off >>= 1) s += __shfl_down_sync(0xffffffffu, s, off);
    if (lane == 0) gbeta[b * QKV_M + o] = s + b_qkv[o];
}

// -------------------- fp16 helpers -----------------------------------------
__device__ __forceinline__ uint32_t pkh2(float lo, float hi) {
    __half2 h = __floats2half2_rn(lo, hi);   // lo -> .x (low 16 bits)
    return *(uint32_t*)&h;
}

__device__ __forceinline__ void mma_f16(float* c,
    uint32_t a0, uint32_t a1, uint32_t a2, uint32_t a3,
    uint32_t b0, uint32_t b1)
{
    asm volatile(
        "mma.sync.aligned.m16n8k16.row.col.f32.f16.f16.f32 "
        "{%0,%1,%2,%3}, {%4,%5,%6,%7}, {%8,%9}, {%0,%1,%2,%3};"
        : "+f"(c[0]), "+f"(c[1]), "+f"(c[2]), "+f"(c[3])
        : "r"(a0), "r"(a1), "r"(a2), "r"(a3), "r"(b0), "r"(b1));
}

// -------------------- fp16 tensor-core 128x128 GEMM (k-stage 32) ------------
// C[b](MxN) = (A[b] scaled along K by scale[b]) @ B[b] + bias[b][row]
// A row-major [M][K] fp32, B row-major [K][N] fp32, K multiple of 32.
// Smem holds half2 packed along k.
__global__ void __launch_bounds__(256) gemm_f16(
    const float* __restrict__ Abase, long sA,
    const float* __restrict__ scaleBase, long sScale,
    const float* __restrict__ Bbase, long sB,
    const float* __restrict__ biasBase, long sBias,
    float* __restrict__ Cbase, long sC,
    int N, int K)
{
    const float* A    = Abase + (long)blockIdx.z * sA;
    const float* Bp   = Bbase + (long)blockIdx.z * sB;
    const float* bias = biasBase + (long)blockIdx.z * sBias;
    const float* scale = scaleBase ? scaleBase + (long)blockIdx.z * sScale : nullptr;
    float* C = Cbase + (long)blockIdx.z * sC;

    // As: [m 128][k2 16 used, stride 20] half2-along-k. Fragment LDS: bank =
    //     (20*m + c) mod 32 -> all 32 lanes distinct (20*g pattern covers 8
    //     distinct groups of 4).
    // Bs: [k2 16][n 128, stride 132]. Fragment LDS: bank = (4*(k2)+n) mod 32,
    //     4*tig+g covers all 32 banks.
    __shared__ uint32_t As[128][20];
    __shared__ uint32_t Bs[16][132];

    int tid  = threadIdx.x;
    int lane = tid & 31, warp = tid >> 5;
    int g    = lane >> 2, tig = lane & 3;
    int wm   = (warp & 1) * 64;    // warp m-offset
    int wn   = (warp >> 1) * 32;   // warp n-offset
    int tile_m = blockIdx.y * 128, tile_n = blockIdx.x * 128;

    // A fill: rows ar and ar+64, k-cols akc..akc+7  (2 x float4 per row)
    int ar = tid >> 2, akc = (tid & 3) * 8, ac2 = (tid & 3) * 4;
    // B fill: half2-row bj (k rows 2bj, 2bj+1), n-cols bn..bn+7
    int bj = tid >> 4, bn = (tid & 15) * 8;

    const float* Aptr = A  + (long)(tile_m + ar) * K + akc;
    const float* Bptr = Bp + (long)(2 * bj) * N + tile_n + bn;

    float acc[4][4][4];
    #pragma unroll
    for (int i = 0; i < 4; i++)
        #pragma unroll
        for (int j = 0; j < 4; j++)
            #pragma unroll
            for (int r = 0; r < 4; r++) acc[i][j][r] = 0.f;

    // ---- prefetch stage 0 into registers ----
    float4 aV0 = *(const float4*)Aptr;
    float4 aV1 = *(const float4*)(Aptr + 4);
    float4 aV2 = *(const float4*)(Aptr + (long)64 * K);
    float4 aV3 = *(const float4*)(Aptr + (long)64 * K + 4);
    float4 bV0 = *(const float4*)Bptr;
    float4 bV1 = *(const float4*)(Bptr + 4);
    float4 bV2 = *(const float4*)(Bptr + N);
    float4 bV3 = *(const float4*)(Bptr + N + 4);
    float4 sV0 = {1.f,1.f,1.f,1.f}, sV1 = {1.f,1.f,1.f,1.f};
    if (scale) {
        sV0 = *(const float4*)(scale + akc);
        sV1 = *(const float4*)(scale + akc + 4);
    }

    for (int k0 = 0; k0 < K; k0 += 32) {
        // ---- store stage to smem (scale A, convert to half2) ----
        {
            float4 a0 = aV0, a1 = aV1, a2 = aV2, a3 = aV3;
            a0.x *= sV0.x; a0.y *= sV0.y; a0.z *= sV0.z; a0.w *= sV0.w;
            a1.x *= sV1.x; a1.y *= sV1.y; a1.z *= sV1.z; a1.w *= sV1.w;
            a2.x *= sV0.x; a2.y *= sV0.y; a2.z *= sV0.z; a2.w *= sV0.w;
            a3.x *= sV1.x; a3.y *= sV1.y; a3.z *= sV1.z; a3.w *= sV1.w;
            As[ar][ac2 + 0] = pkh2(a0.x, a0.y);
            As[ar][ac2 + 1] = pkh2(a0.z, a0.w);
            As[ar][ac2 + 2] = pkh2(a1.x, a1.y);
            As[ar][ac2 + 3] = pkh2(a1.z, a1.w);
            As[ar + 64][ac2 + 0] = pkh2(a2.x, a2.y);
            As[ar + 64][ac2 + 1] = pkh2(a2.z, a2.w);
            As[ar + 64][ac2 + 2] = pkh2(a3.x, a3.y);
            As[ar + 64][ac2 + 3] = pkh2(a3.z, a3.w);
            // B: pack (k even, k odd) pairs across the two gmem rows
            Bs[bj][bn + 0] = pkh2(bV0.x, bV2.x);
            Bs[bj][bn + 1] = pkh2(bV0.y, bV2.y);
            Bs[bj][bn + 2] = pkh2(bV0.z, bV2.z);
            Bs[bj][bn + 3] = pkh2(bV0.w, bV2.w);
            Bs[bj][bn + 4] = pkh2(bV1.x, bV3.x);
            Bs[bj][bn + 5] = pkh2(bV1.y, bV3.y);
            Bs[bj][bn + 6] = pkh2(bV1.z, bV3.z);
            Bs[bj][bn + 7] = pkh2(bV1.w, bV3.w);
        }
        __syncthreads();

        // ---- prefetch next stage (overlaps the MMAs below) ----
        if (k0 + 32 < K) {
            Aptr += 32;
            Bptr += (long)32 * N;
            aV0 = *(const float4*)Aptr;
            aV1 = *(const float4*)(Aptr + 4);
            aV2 = *(const float4*)(Aptr + (long)64 * K);
            aV3 = *(const float4*)(Aptr + (long)64 * K + 4);
            bV0 = *(const float4*)Bptr;
            bV1 = *(const float4*)(Bptr + 4);
            bV2 = *(const float4*)(Bptr + N);
            bV3 = *(const float4*)(Bptr + N + 4);
            if (scale) {
                sV0 = *(const float4*)(scale + k0 + 32 + akc);
                sV1 = *(const float4*)(scale + k0 + 32 + akc + 4);
            }
        }

        // ---- compute: 2 k16 sections x 4x4 fragment grid ----
        #pragma unroll
        for (int ks2 = 0; ks2 < 16; ks2 += 8) {
            uint32_t bf[4][2];
            #pragma unroll
            for (int ni = 0; ni < 4; ni++) {
                bf[ni][0] = Bs[ks2 + tig][wn + ni * 8 + g];
                bf[ni][1] = Bs[ks2 + tig + 4][wn + ni * 8 + g];
            }
            #pragma unroll
            for (int mi = 0; mi < 4; mi++) {
                int m0 = wm + mi * 16 + g;
                uint32_t a0 = As[m0][ks2 + tig];
                uint32_t a1 = As[m0 + 8][ks2 + tig];
                uint32_t a2 = As[m0][ks2 + tig + 4];
                uint32_t a3 = As[m0 + 8][ks2 + tig + 4];
                #pragma unroll
                for (int ni = 0; ni < 4; ni++)
                    mma_f16(acc[mi][ni], a0, a1, a2, a3, bf[ni][0], bf[ni][1]);
            }
        }
        __syncthreads();
    }

    // ---- epilogue: +bias, float2 stores ----
    #pragma unroll
    for (int mi = 0; mi < 4; mi++) {
        int r0 = tile_m + wm + mi * 16 + g;
        int r1 = r0 + 8;
        float bv0 = bias[r0], bv1 = bias[r1];
        #pragma unroll
        for (int ni = 0; ni < 4; ni++) {
            int col = tile_n + wn + ni * 8 + 2 * tig;
            float2 v0 = {acc[mi][ni][0] + bv0, acc[mi][ni][1] + bv0};
            float2 v1 = {acc[mi][ni][2] + bv1, acc[mi][ni][3] + bv1};
            *(float2*)(C + (long)r0 * N + col) = v0;
            *(float2*)(C + (long)r1 * N + col) = v1;
        }
    }
}

// -------------------- K5: partial context + partial Z -----------------------
__global__ void __launch_bounds__(256) k5_ctx_partial(
    const float* __restrict__ qkv, float* __restrict__ pctx, float* __restrict__ pZ)
{
    int split = blockIdx.x, h = blockIdx.y, b = blockIdx.z;
    const float* kb = qkv + ((size_t)b * QKV_M + 512  + h * HDIM) * WW + split * 512;
    const float* vb = qkv + ((size_t)b * QKV_M + 1024 + h * HDIM) * WW + split * 512;

    __shared__ float ekT[16][64];
    __shared__ float vT [16][64];
    int tid = threadIdx.x;
    int ld_d = tid >> 2, ld_n4 = (tid & 3) << 2;
    int ty = tid >> 4, tx = tid & 15;

    float acc[4][4];
    #pragma unroll
    for (int i = 0; i < 4; i++)
        #pragma unroll
        for (int j = 0; j < 4; j++) acc[i][j] = 0.f;
    float zacc = 0.f;

    for (int nc = 0; nc < 512; nc += 16) {
        float4 kv4 = *(const float4*)(kb + (long)ld_d * WW + nc + ld_n4);
        float4 vv4 = *(const float4*)(vb + (long)ld_d * WW + nc + ld_n4);
        ekT[ld_n4 + 0][ld_d] = __expf(kv4.x);
        ekT[ld_n4 + 1][ld_d] = __expf(kv4.y);
        ekT[ld_n4 + 2][ld_d] = __expf(kv4.z);
        ekT[ld_n4 + 3][ld_d] = __expf(kv4.w);
        vT [ld_n4 + 0][ld_d] = vv4.x;
        vT [ld_n4 + 1][ld_d] = vv4.y;
        vT [ld_n4 + 2][ld_d] = vv4.z;
        vT [ld_n4 + 3][ld_d] = vv4.w;
        __syncthreads();

        if (tid < 64) {
            #pragma unroll
            for (int nn = 0; nn < 16; nn++) zacc += ekT[nn][tid];
        }
        #pragma unroll
        for (int nn = 0; nn < 16; nn++) {
            float a0[4], b0[4];
            *(float4*)a0 = *(const float4*)&ekT[nn][ty * 4];
            *(float4*)b0 = *(const float4*)&vT [nn][tx * 4];
            #pragma unroll
            for (int i = 0; i < 4; i++)
                #pragma unroll
                for (int j = 0; j < 4; j++)
                    acc[i][j] += a0[i] * b0[j];
        }
        __syncthreads();
    }

    size_t base = (((size_t)(b * HEADS + h)) * SPLITS + split) * (HDIM * HDIM);
    #pragma unroll
    for (int i = 0; i < 4; i++)
        #pragma unroll
        for (int j = 0; j < 4; j++)
            pctx[base + (ty * 4 + i) * HDIM + tx * 4 + j] = acc[i][j];
    if (tid < 64)
        pZ[((b * HEADS + h) * SPLITS + split) * HDIM + tid] = zacc;
}

// -------------------- K5b: reduce splits + normalize ------------------------
__global__ void __launch_bounds__(256) k5b_reduce(
    const float* __restrict__ pctx, const float* __restrict__ pZ, float* __restrict__ ctx)
{
    int bh = blockIdx.x;
    __shared__ float zs[64];
    if (threadIdx.x < 64) {
        float z = 0.f;
        #pragma unroll
        for (int s = 0; s < SPLITS; s++) z += pZ[(bh * SPLITS + s) * HDIM + threadIdx.x];
        zs[threadIdx.x] = 1.f / z;
    }
    __syncthreads();
    for (int idx = threadIdx.x; idx < HDIM * HDIM; idx += 256) {
        float a = 0.f;
        #pragma unroll
        for (int s = 0; s < SPLITS; s++)
            a += pctx[((size_t)bh * SPLITS + s) * (HDIM * HDIM) + idx];
        ctx[(size_t)bh * (HDIM * HDIM) + idx] = a * zs[idx >> 6];
    }
}

// -------------------- K6: Wc[b][o][h*64+d] = sum_e w_out[o,he] ctx[h,d,e] ---
__global__ void __launch_bounds__(256) k6_wc(
    const float* __restrict__ w_out, const float* __restrict__ ctx, float* __restrict__ Wc)
{
    int h = blockIdx.x, b = blockIdx.y;
    __shared__ float cs[64][65];
    int bh = b * HEADS + h;
    for (int t = threadIdx.x; t < HDIM * HDIM; t += 256)
        cs[t >> 6][t & 63] = ctx[(size_t)bh * (HDIM * HDIM) + t];
    __syncthreads();

    #pragma unroll
    for (int rep = 0; rep < 2; rep++) {
        int o = (rep << 8) + threadIdx.x;
        const float* wrow = w_out + (size_t)o * CH + h * HDIM;
        float wc[64];
        #pragma unroll
        for (int e = 0; e < 64; e++) wc[e] = wrow[e];
        float* outp = Wc + ((size_t)b * CH + o) * CH + h * HDIM;
        for (int d = 0; d < 64; d++) {
            float s = 0.f;
            #pragma unroll
            for (int e = 0; e < 64; e++) s += wc[e] * cs[d][e];
            outp[d] = s;
        }
    }
}

// -------------------- launch -----------------------------------------------
extern "C" void kernel_launch(void* const* d_in, const int* in_sizes, int n_in,
                              void* d_out, int out_size)
{
    const float* x     = (const float*)d_in[0];
    const float* gn_w  = (const float*)d_in[1];
    const float* gn_b  = (const float*)d_in[2];
    const float* w_qkv = (const float*)d_in[3];
    const float* b_qkv = (const float*)d_in[4];
    const float* w_out = (const float*)d_in[5];
    const float* b_out = (const float*)d_in[6];
    float* out = (float*)d_out;

    float *p_qkv, *p_a, *p_bb, *p_beta, *p_pctx, *p_pZ, *p_ctx, *p_Wc;
    cudaGetSymbolAddress((void**)&p_qkv,  g_qkv);
    cudaGetSymbolAddress((void**)&p_a,    g_a);
    cudaGetSymbolAddress((void**)&p_bb,   g_bb);
    cudaGetSymbolAddress((void**)&p_beta, g_beta);
    cudaGetSymbolAddress((void**)&p_pctx, g_pctx);
    cudaGetSymbolAddress((void**)&p_pZ,   g_pZ);
    cudaGetSymbolAddress((void**)&p_ctx,  g_ctx);
    cudaGetSymbolAddress((void**)&p_Wc,   g_Wc);

    // K1: group stats
    k1_stats<<<BATCH * GROUPS, 256>>>(x, gn_w, gn_b, p_a, p_bb);

    // K2: folded bias
    k2_beta<<<dim3(QKV_M / 8, BATCH), 256>>>(w_qkv, b_qkv, p_bb, p_beta);

    // K3: QKV GEMM (fp16 tensor cores; A = w_qkv scaled by a[b] along K)
    gemm_f16<<<dim3(WW / 128, QKV_M / 128, BATCH), 256>>>(
        w_qkv, 0L,
        p_a, (long)CH,
        x, (long)CH * WW,
        p_beta, (long)QKV_M,
        p_qkv, (long)QKV_M * WW,
        WW, CH);

    // K5: context partials (+Z)
    k5_ctx_partial<<<dim3(SPLITS, HEADS, BATCH), 256>>>(p_qkv, p_pctx, p_pZ);

    // K5b: reduce + normalize
    k5b_reduce<<<BATCH * HEADS, 256>>>(p_pctx, p_pZ, p_ctx);

    // K6: fold out-projection with context
    k6_wc<<<dim3(HEADS, BATCH), 256>>>(w_out, p_ctx, p_Wc);

    // K7: final GEMM (fp16 tensor cores)  out[b] = Wc[b] @ q[b] + b_out
    gemm_f16<<<dim3(WW / 128, CH / 128, BATCH), 256>>>(
        p_Wc, (long)CH * CH,
        nullptr, 0L,
        p_qkv, (long)QKV_M * WW,   // q = rows [0,512) of qkv[b]
        b_out, 0L,
        out, (long)CH * WW,
        WW, CH);
}